// round 13
// baseline (speedup 1.0000x reference)
#include <cuda_runtime.h>
#include <cstdint>

#define CIN 64
#define COUT 64
#define NOFFS 26
#define NTAPS 27
#define CSLICES 26
#define YTOT (NOFFS + CSLICES)     // 52
#define THREADS 128
#define WPB (THREADS / 32)         // 4 warps per block
#define GP 16                      // pairs per warp iteration (one M=16 tile)
#define GRIDX 11                   // 11*52 = 572 blocks = 1 wave @ 4/SM

#define BWS_U32 (32 * 32 * 4)                    // 16384 B
#define SBUF_F 68                                // staged row stride (floats)
#define SBUF_WORDS (2 * GP * SBUF_F)             // per-warp double buffer
#define SMEM_BYTES ((BWS_U32 + WPB * SBUF_WORDS) * 4)   // 51200 B

typedef uint32_t u32;

// ---- bf16 split helpers -----------------------------------------------------
__device__ __forceinline__ u32 pack_bf16x2(float even, float odd) {
    u32 r;
    asm("cvt.rn.bf16x2.f32 %0, %1, %2;" : "=r"(r) : "f"(odd), "f"(even));
    return r;
}
__device__ __forceinline__ float lo_elem_f(u32 h) { return __uint_as_float(h << 16); }
__device__ __forceinline__ float hi_elem_f(u32 h) { return __uint_as_float(h & 0xffff0000u); }
__device__ __forceinline__ void split2(float e, float o, u32& hp, u32& lp) {
    hp = pack_bf16x2(e, o);
    lp = pack_bf16x2(e - lo_elem_f(hp), o - hi_elem_f(hp));
}

// D += A(16x16 bf16,row) * B(16x8 bf16,col), f32 accumulate
__device__ __forceinline__ void mma_bf16_v(float c[4], u32 a0, u32 a1, u32 a2,
                                           u32 a3, u32 b0, u32 b1) {
    asm volatile(
        "mma.sync.aligned.m16n8k16.row.col.f32.bf16.bf16.f32 "
        "{%0,%1,%2,%3}, {%4,%5,%6,%7}, {%8,%9}, {%0,%1,%2,%3};"
        : "+f"(c[0]), "+f"(c[1]), "+f"(c[2]), "+f"(c[3])
        : "r"(a0), "r"(a1), "r"(a2), "r"(a3), "r"(b0), "r"(b1));
}

// ---- cp.async helpers --------------------------------------------------------
__device__ __forceinline__ u32 smem_u32ptr(const void* p) {
    return (u32)__cvta_generic_to_shared(p);
}
__device__ __forceinline__ void cp_async16(u32 dst, const void* src) {
    asm volatile("cp.async.cg.shared.global [%0], [%1], 16;"
                 :: "r"(dst), "l"(src));
}
__device__ __forceinline__ void cp_commit() {
    asm volatile("cp.async.commit_group;");
}
__device__ __forceinline__ void cp_wait1() {
    asm volatile("cp.async.wait_group 1;");
}

// Build B fragments (hi/lo bf16 split) for tap t in mma lane layout.
__device__ __forceinline__ void build_b_tiles(uint4* bws,
                                              const float* __restrict__ weight,
                                              int t) {
    for (int idx = threadIdx.x; idx < 32 * 32; idx += THREADS) {
        int lane = idx & 31, tile = idx >> 5;
        int kt = tile >> 3, nt = tile & 7;
        int n  = nt * 8 + (lane >> 2);
        int k0 = kt * 16 + 2 * (lane & 3);
        const float* wrow = weight + ((long)n * NTAPS + t) * CIN;
        float w0 = __ldg(&wrow[k0]),     w1 = __ldg(&wrow[k0 + 1]);
        float w8 = __ldg(&wrow[k0 + 8]), w9 = __ldg(&wrow[k0 + 9]);
        u32 bh0, bl0, bh1, bl1;
        split2(w0, w1, bh0, bl0);
        split2(w8, w9, bh1, bl1);
        bws[idx] = make_uint4(bh0, bh1, bl0, bl1);
    }
}

// ----------------------------------------------------------------------------
// Fused kernel. blockIdx.y:
//   0..25  -> neighbor-offset scatter (pairs from nei), C starts at 0
//   26..51 -> center slices (pairs = (v,v)),            C starts at bias
// Identical cp.async double-buffered gather -> MMA -> atomicAdd pipeline.
// Output must be pre-zeroed (memset); every contribution is atomic.
// ----------------------------------------------------------------------------
__global__ __launch_bounds__(THREADS, 4)
void conv_kernel(const float* __restrict__ sp,
                 const float* __restrict__ weight,
                 const float* __restrict__ bias,
                 const int2* __restrict__ nei,
                 const int* __restrict__ sizes,
                 float* __restrict__ out,
                 int P, int n_vox, int chunk) {
    extern __shared__ u32 smem_raw[];
    uint4* bws = (uint4*)smem_raw;

    const int o = blockIdx.y;
    const bool is_center = (o >= NOFFS);
    const int t = is_center ? 13 : (o < 13 ? o : o + 1);

    build_b_tiles(bws, weight, t);
    __syncthreads();

    int size, start = 0;
    long pair_base = 0;
    if (is_center) {
        start = (o - NOFFS) * chunk;
        size = n_vox - start;
        if (size > chunk) size = chunk;
        if (size <= 0) return;
    } else {
        size = sizes[o];
        if (size <= 0) return;
        pair_base = (long)o * P;
    }

    const int lane = threadIdx.x & 31;
    const int wid  = threadIdx.x >> 5;
    const int tig  = lane & 3;
    const int g    = lane >> 2;

    // C initializer: center rides the bias along (one center contrib per row)
    float cinit[8][2];
#pragma unroll
    for (int nt = 0; nt < 8; nt++) {
        if (is_center) {
            float2 b = __ldg((const float2*)bias + nt * 4 + tig);
            cinit[nt][0] = b.x; cinit[nt][1] = b.y;
        } else {
            cinit[nt][0] = 0.f; cinit[nt][1] = 0.f;
        }
    }

    // per-warp double buffer: [buf][row][SBUF_F]
    float* mybuf = (float*)(smem_raw + BWS_U32 + wid * SBUF_WORDS);
    const int srow_half = lane >> 4;       // 0/1
    const int schunk    = lane & 15;       // 16B chunk within 256B row
    const u32 dst_base  = smem_u32ptr(mybuf) + schunk * 16;

    const int ngroups = (size + GP - 1) / GP;
    const int stride  = gridDim.x * WPB;
    int grp = blockIdx.x * WPB + wid;
    if (grp >= ngroups) return;

    // index fetch: lanes 0..15 hold the group's (out,in) pairs
    auto fetch_idx = [&](int gq) -> int2 {
        int p = gq * GP + lane;
        if (p >= size) p = size - 1;
        if (is_center) {
            int v = start + p;
            return make_int2(v, v);
        }
        int2 r = make_int2(0, 0);
        if (lane < GP) r = __ldg(&nei[pair_base + p]);
        return r;
    };

    auto issue_group = [&](int2 pr, int b) {
        u32 dst = dst_base + (u32)b * (GP * SBUF_F * 4);
#pragma unroll
        for (int i = 0; i < 8; i++) {
            int row = 2 * i + srow_half;
            int ii  = __shfl_sync(0xffffffffu, pr.y, row);
            cp_async16(dst + row * (SBUF_F * 4),
                       sp + (long)ii * CIN + schunk * 4);
        }
    };

    int2 pr_cur = fetch_idx(grp);
    issue_group(pr_cur, 0);
    cp_commit();
    int2 pr_nxt = make_int2(0, 0);
    if (grp + stride < ngroups) pr_nxt = fetch_idx(grp + stride);

    int buf = 0;
    for (; grp < ngroups;) {
        const int next = grp + stride;

        if (next < ngroups) issue_group(pr_nxt, buf ^ 1);
        cp_commit();

        int2 pr_n2 = make_int2(0, 0);
        if (next + stride < ngroups) pr_n2 = fetch_idx(next + stride);

        cp_wait1();
        __syncwarp();

        const int base_p = grp * GP;
        const float* rows = mybuf + buf * (GP * SBUF_F);
        const float* r0 = rows + g * SBUF_F;
        const float* r1 = rows + (g + 8) * SBUF_F;

        float C[8][4];
#pragma unroll
        for (int nt = 0; nt < 8; nt++) {
            C[nt][0] = cinit[nt][0]; C[nt][1] = cinit[nt][1];
            C[nt][2] = cinit[nt][0]; C[nt][3] = cinit[nt][1];
        }

#pragma unroll
        for (int kt = 0; kt < 4; kt++) {
            const int c0 = 16 * kt + 2 * tig;
            float2 f0 = *(const float2*)(r0 + c0);
            float2 f1 = *(const float2*)(r1 + c0);
            float2 f2 = *(const float2*)(r0 + c0 + 8);
            float2 f3 = *(const float2*)(r1 + c0 + 8);

            u32 x0h, x0l, x1h, x1l, x2h, x2l, x3h, x3l;
            split2(f0.x, f0.y, x0h, x0l);
            split2(f1.x, f1.y, x1h, x1l);
            split2(f2.x, f2.y, x2h, x2l);
            split2(f3.x, f3.y, x3h, x3l);

#pragma unroll
            for (int nt = 0; nt < 8; nt++) {
                uint4 b = bws[(kt * 8 + nt) * 32 + lane];
                mma_bf16_v(C[nt], x0h, x1h, x2h, x3h, b.x, b.y);  // Ah*Bh
                mma_bf16_v(C[nt], x0l, x1l, x2l, x3l, b.x, b.y);  // Al*Bh
                mma_bf16_v(C[nt], x0h, x1h, x2h, x3h, b.z, b.w);  // Ah*Bl
            }
        }

        // atomic scatter: rows g (c0,c1) and g+8 (c2,c3)
        int oi0 = __shfl_sync(0xffffffffu, pr_cur.x, g);
        int oi1 = __shfl_sync(0xffffffffu, pr_cur.x, g + 8);
        bool v0 = (base_p + g)     < size;
        bool v1 = (base_p + g + 8) < size;
        float* o0 = out + (long)oi0 * COUT + 2 * tig;
        float* o1 = out + (long)oi1 * COUT + 2 * tig;
#pragma unroll
        for (int nt = 0; nt < 8; nt++) {
            if (v0)
                atomicAdd((float2*)(o0 + nt * 8),
                          make_float2(C[nt][0], C[nt][1]));
            if (v1)
                atomicAdd((float2*)(o1 + nt * 8),
                          make_float2(C[nt][2], C[nt][3]));
        }

        pr_cur = pr_nxt;
        pr_nxt = pr_n2;
        buf ^= 1;
        grp = next;
    }
}

// ----------------------------------------------------------------------------
extern "C" void kernel_launch(void* const* d_in, const int* in_sizes, int n_in,
                              void* d_out, int out_size) {
    const float* sp     = (const float*)d_in[0];   // [N, 64]
    const float* weight = (const float*)d_in[1];   // [64, 3,3,3, 64]
    const float* bias   = (const float*)d_in[2];   // [64]
    const int2*  nei    = (const int2*)d_in[3];    // [26, P, 2] -> int2 pairs
    const int*   sizes  = (const int*)d_in[4];     // [26]
    float* out = (float*)d_out;

    const int n_vox = in_sizes[0] / CIN;
    const int P     = in_sizes[3] / (NOFFS * 2);
    const int chunk = (n_vox + CSLICES - 1) / CSLICES;

    cudaFuncSetAttribute(conv_kernel,
                         cudaFuncAttributeMaxDynamicSharedMemorySize,
                         SMEM_BYTES);

    // zero output; all contributions (incl. center+bias) accumulate atomically
    cudaMemsetAsync(out, 0, (size_t)out_size * sizeof(float), 0);

    dim3 grid(GRIDX, YTOT, 1);
    conv_kernel<<<grid, THREADS, SMEM_BYTES>>>(sp, weight, bias, nei, sizes,
                                               out, P, n_vox, chunk);
}

// round 14
// speedup vs baseline: 1.0517x; 1.0517x over previous
#include <cuda_runtime.h>
#include <cstdint>

#define CIN 64
#define COUT 64
#define NOFFS 26
#define NTAPS 27

// center kernel config
#define CTHREADS 128
#define CWPB (CTHREADS / 32)
#define CGP 32

// scatter kernel config
#define STHREADS 128
#define SWPB (STHREADS / 32)
#define SGP 16
#define SGRIDX 22                  // 22*26 = 572 blocks ≈ 1 wave @ 4/SM

#define BWS_U32 (32 * 32 * 4)                    // 16384 B
#define SBUF_F 68                                // staged row stride (floats)
#define SBUF_WORDS (2 * SGP * SBUF_F)            // per-warp double buffer
#define SMEM_SC_BYTES ((BWS_U32 + SWPB * SBUF_WORDS) * 4)   // 51200 B
#define SMEM_C_BYTES (BWS_U32 * 4)

typedef uint32_t u32;

// ---- bf16 split helpers -----------------------------------------------------
__device__ __forceinline__ u32 pack_bf16x2(float even, float odd) {
    u32 r;
    asm("cvt.rn.bf16x2.f32 %0, %1, %2;" : "=r"(r) : "f"(odd), "f"(even));
    return r;
}
__device__ __forceinline__ float lo_elem_f(u32 h) { return __uint_as_float(h << 16); }
__device__ __forceinline__ float hi_elem_f(u32 h) { return __uint_as_float(h & 0xffff0000u); }
__device__ __forceinline__ void split2(float e, float o, u32& hp, u32& lp) {
    hp = pack_bf16x2(e, o);
    lp = pack_bf16x2(e - lo_elem_f(hp), o - hi_elem_f(hp));
}

// D += A(16x16 bf16,row) * B(16x8 bf16,col), f32 accumulate
__device__ __forceinline__ void mma_bf16_v(float c[4], u32 a0, u32 a1, u32 a2,
                                           u32 a3, u32 b0, u32 b1) {
    asm volatile(
        "mma.sync.aligned.m16n8k16.row.col.f32.bf16.bf16.f32 "
        "{%0,%1,%2,%3}, {%4,%5,%6,%7}, {%8,%9}, {%0,%1,%2,%3};"
        : "+f"(c[0]), "+f"(c[1]), "+f"(c[2]), "+f"(c[3])
        : "r"(a0), "r"(a1), "r"(a2), "r"(a3), "r"(b0), "r"(b1));
}

// ---- cp.async helpers --------------------------------------------------------
__device__ __forceinline__ u32 smem_u32ptr(const void* p) {
    return (u32)__cvta_generic_to_shared(p);
}
__device__ __forceinline__ void cp_async16(u32 dst, const void* src) {
    asm volatile("cp.async.cg.shared.global [%0], [%1], 16;"
                 :: "r"(dst), "l"(src));
}
__device__ __forceinline__ void cp_commit() {
    asm volatile("cp.async.commit_group;");
}
__device__ __forceinline__ void cp_wait1() {
    asm volatile("cp.async.wait_group 1;");
}

// Permuted output-column map: tile nt, hw tile-col c (0..7) ->
// global co = (c>>1)*16 + nt*2 + (c&1).
// Lane (g, tig) then owns 16 CONSECUTIVE output cols [tig*16, tig*16+16).
// Build B fragments (hi/lo bf16 split) for tap t with this mapping.
template <int NT>
__device__ __forceinline__ void build_b_tiles(uint4* bws,
                                              const float* __restrict__ weight,
                                              int t) {
    for (int idx = threadIdx.x; idx < 32 * 32; idx += NT) {
        int lane = idx & 31, tile = idx >> 5;
        int kt = tile >> 3, nt = tile & 7;
        int j  = lane >> 2;                        // hw tile-col 0..7
        int n  = (j >> 1) * 16 + nt * 2 + (j & 1); // permuted global co
        int k0 = kt * 16 + 2 * (lane & 3);
        const float* wrow = weight + ((long)n * NTAPS + t) * CIN;
        float w0 = __ldg(&wrow[k0]),     w1 = __ldg(&wrow[k0 + 1]);
        float w8 = __ldg(&wrow[k0 + 8]), w9 = __ldg(&wrow[k0 + 9]);
        u32 bh0, bl0, bh1, bl1;
        split2(w0, w1, bh0, bl0);
        split2(w8, w9, bh1, bl1);
        bws[idx] = make_uint4(bh0, bh1, bl0, bl1);
    }
}

// ----------------------------------------------------------------------------
// Center kernel: out[v] = bias + sp[v] @ Wc  -- STG.128 stores, initializes out.
// ----------------------------------------------------------------------------
__global__ __launch_bounds__(CTHREADS, 4)
void center_kernel(const float* __restrict__ sp,
                   const float* __restrict__ weight,
                   const float* __restrict__ bias,
                   float* __restrict__ out, int n_vox) {
    extern __shared__ u32 smem_raw[];
    uint4* bws = (uint4*)smem_raw;

    build_b_tiles<CTHREADS>(bws, weight, 13);
    __syncthreads();

    const int lane = threadIdx.x & 31;
    const int wid  = threadIdx.x >> 5;
    const int tig  = lane & 3;
    const int g    = lane >> 2;

    // bias fragment for this lane's 16 consecutive cols
    float4 b4[4];
#pragma unroll
    for (int q = 0; q < 4; q++)
        b4[q] = __ldg((const float4*)bias + tig * 4 + q);

    const int ngroups = (n_vox + CGP - 1) / CGP;

    for (int grp = blockIdx.x * CWPB + wid; grp < ngroups;
         grp += gridDim.x * CWPB) {
        const int base_v = grp * CGP;

        int v0 = base_v + g;        if (v0 >= n_vox) v0 = n_vox - 1;
        int v1 = base_v + g + 8;    if (v1 >= n_vox) v1 = n_vox - 1;
        int v2 = base_v + g + 16;   if (v2 >= n_vox) v2 = n_vox - 1;
        int v3 = base_v + g + 24;   if (v3 >= n_vox) v3 = n_vox - 1;
        const float* r0 = sp + (long)v0 * CIN;
        const float* r1 = sp + (long)v1 * CIN;
        const float* r2 = sp + (long)v2 * CIN;
        const float* r3 = sp + (long)v3 * CIN;

        float C[2][8][4];
#pragma unroll
        for (int m = 0; m < 2; m++)
#pragma unroll
            for (int nt = 0; nt < 8; nt++) {
                C[m][nt][0] = 0.f; C[m][nt][1] = 0.f;
                C[m][nt][2] = 0.f; C[m][nt][3] = 0.f;
            }

#pragma unroll
        for (int kt = 0; kt < 4; kt++) {
            const int c0 = 16 * kt + 2 * tig;
            float2 f0 = __ldg((const float2*)(r0 + c0));
            float2 f1 = __ldg((const float2*)(r1 + c0));
            float2 f2 = __ldg((const float2*)(r0 + c0 + 8));
            float2 f3 = __ldg((const float2*)(r1 + c0 + 8));
            float2 e0 = __ldg((const float2*)(r2 + c0));
            float2 e1 = __ldg((const float2*)(r3 + c0));
            float2 e2 = __ldg((const float2*)(r2 + c0 + 8));
            float2 e3 = __ldg((const float2*)(r3 + c0 + 8));

            u32 x0h, x0l, x1h, x1l, x2h, x2l, x3h, x3l;
            split2(f0.x, f0.y, x0h, x0l);
            split2(f1.x, f1.y, x1h, x1l);
            split2(f2.x, f2.y, x2h, x2l);
            split2(f3.x, f3.y, x3h, x3l);
            u32 y0h, y0l, y1h, y1l, y2h, y2l, y3h, y3l;
            split2(e0.x, e0.y, y0h, y0l);
            split2(e1.x, e1.y, y1h, y1l);
            split2(e2.x, e2.y, y2h, y2l);
            split2(e3.x, e3.y, y3h, y3l);

#pragma unroll
            for (int nt = 0; nt < 8; nt++) {
                uint4 b = bws[(kt * 8 + nt) * 32 + lane];
                mma_bf16_v(C[0][nt], x0h, x1h, x2h, x3h, b.x, b.y);
                mma_bf16_v(C[0][nt], x0l, x1l, x2l, x3l, b.x, b.y);
                mma_bf16_v(C[0][nt], x0h, x1h, x2h, x3h, b.z, b.w);
                mma_bf16_v(C[1][nt], y0h, y1h, y2h, y3h, b.x, b.y);
                mma_bf16_v(C[1][nt], y0l, y1l, y2l, y3l, b.x, b.y);
                mma_bf16_v(C[1][nt], y0h, y1h, y2h, y3h, b.z, b.w);
            }
        }

        // STG.128 stores: lane covers cols [tig*16, tig*16+16) of its rows
#pragma unroll
        for (int m = 0; m < 2; m++) {
            int w0 = base_v + 16 * m + g;
            int w1 = w0 + 8;
            float* p0 = out + (long)w0 * COUT + tig * 16;
            float* p1 = out + (long)w1 * COUT + tig * 16;
#pragma unroll
            for (int q = 0; q < 4; q++) {
                if (w0 < n_vox)
                    *(float4*)(p0 + 4 * q) = make_float4(
                        C[m][2 * q][0] + b4[q].x, C[m][2 * q][1] + b4[q].y,
                        C[m][2 * q + 1][0] + b4[q].z,
                        C[m][2 * q + 1][1] + b4[q].w);
                if (w1 < n_vox)
                    *(float4*)(p1 + 4 * q) = make_float4(
                        C[m][2 * q][2] + b4[q].x, C[m][2 * q][3] + b4[q].y,
                        C[m][2 * q + 1][2] + b4[q].z,
                        C[m][2 * q + 1][3] + b4[q].w);
            }
        }
    }
}

// ----------------------------------------------------------------------------
// Scatter kernel: cp.async double-buffered gather, float4 (RED.128) epilogue.
// ----------------------------------------------------------------------------
__global__ __launch_bounds__(STHREADS, 4)
void scatter_kernel(const float* __restrict__ sp,
                    const float* __restrict__ weight,
                    const int2* __restrict__ nei,
                    const int* __restrict__ sizes,
                    float* __restrict__ out, int P) {
    extern __shared__ u32 smem_raw[];
    uint4* bws = (uint4*)smem_raw;

    const int o = blockIdx.y;
    const int t = (o < 13) ? o : o + 1;

    build_b_tiles<STHREADS>(bws, weight, t);
    __syncthreads();

    const int size = sizes[o];
    if (size <= 0) return;
    const long pair_base = (long)o * P;

    const int lane = threadIdx.x & 31;
    const int wid  = threadIdx.x >> 5;
    const int tig  = lane & 3;
    const int g    = lane >> 2;

    float* mybuf = (float*)(smem_raw + BWS_U32 + wid * SBUF_WORDS);
    const int srow_half = lane >> 4;
    const int schunk    = lane & 15;
    const u32 dst_base  = smem_u32ptr(mybuf) + schunk * 16;

    const int ngroups = (size + SGP - 1) / SGP;
    const int stride  = gridDim.x * SWPB;
    int grp = blockIdx.x * SWPB + wid;
    if (grp >= ngroups) return;

    auto fetch_idx = [&](int gq) -> int2 {
        int p = gq * SGP + lane;
        if (p >= size) p = size - 1;
        int2 r = make_int2(0, 0);
        if (lane < SGP) r = __ldg(&nei[pair_base + p]);
        return r;
    };

    auto issue_group = [&](int2 pr, int b) {
        u32 dst = dst_base + (u32)b * (SGP * SBUF_F * 4);
#pragma unroll
        for (int i = 0; i < 8; i++) {
            int row = 2 * i + srow_half;
            int ii  = __shfl_sync(0xffffffffu, pr.y, row);
            cp_async16(dst + row * (SBUF_F * 4),
                       sp + (long)ii * CIN + schunk * 4);
        }
    };

    int2 pr_cur = fetch_idx(grp);
    issue_group(pr_cur, 0);
    cp_commit();
    int2 pr_nxt = make_int2(0, 0);
    if (grp + stride < ngroups) pr_nxt = fetch_idx(grp + stride);

    int buf = 0;
    for (; grp < ngroups;) {
        const int next = grp + stride;

        if (next < ngroups) issue_group(pr_nxt, buf ^ 1);
        cp_commit();

        int2 pr_n2 = make_int2(0, 0);
        if (next + stride < ngroups) pr_n2 = fetch_idx(next + stride);

        cp_wait1();
        __syncwarp();

        const int base_p = grp * SGP;
        const float* rows = mybuf + buf * (SGP * SBUF_F);
        const float* r0 = rows + g * SBUF_F;
        const float* r1 = rows + (g + 8) * SBUF_F;

        float C[8][4];
#pragma unroll
        for (int nt = 0; nt < 8; nt++) {
            C[nt][0] = 0.f; C[nt][1] = 0.f; C[nt][2] = 0.f; C[nt][3] = 0.f;
        }

#pragma unroll
        for (int kt = 0; kt < 4; kt++) {
            const int c0 = 16 * kt + 2 * tig;
            float2 f0 = *(const float2*)(r0 + c0);
            float2 f1 = *(const float2*)(r1 + c0);
            float2 f2 = *(const float2*)(r0 + c0 + 8);
            float2 f3 = *(const float2*)(r1 + c0 + 8);

            u32 x0h, x0l, x1h, x1l, x2h, x2l, x3h, x3l;
            split2(f0.x, f0.y, x0h, x0l);
            split2(f1.x, f1.y, x1h, x1l);
            split2(f2.x, f2.y, x2h, x2l);
            split2(f3.x, f3.y, x3h, x3l);

#pragma unroll
            for (int nt = 0; nt < 8; nt++) {
                uint4 b = bws[(kt * 8 + nt) * 32 + lane];
                mma_bf16_v(C[nt], x0h, x1h, x2h, x3h, b.x, b.y);  // Ah*Bh
                mma_bf16_v(C[nt], x0l, x1l, x2l, x3l, b.x, b.y);  // Al*Bh
                mma_bf16_v(C[nt], x0h, x1h, x2h, x3h, b.z, b.w);  // Ah*Bl
            }
        }

        // RED.128 scatter: lane covers cols [tig*16, tig*16+16)
        int oi0 = __shfl_sync(0xffffffffu, pr_cur.x, g);
        int oi1 = __shfl_sync(0xffffffffu, pr_cur.x, g + 8);
        bool v0 = (base_p + g)     < size;
        bool v1 = (base_p + g + 8) < size;
        float* o0 = out + (long)oi0 * COUT + tig * 16;
        float* o1 = out + (long)oi1 * COUT + tig * 16;
#pragma unroll
        for (int q = 0; q < 4; q++) {
            if (v0)
                atomicAdd((float4*)(o0 + 4 * q),
                          make_float4(C[2 * q][0], C[2 * q][1],
                                      C[2 * q + 1][0], C[2 * q + 1][1]));
            if (v1)
                atomicAdd((float4*)(o1 + 4 * q),
                          make_float4(C[2 * q][2], C[2 * q][3],
                                      C[2 * q + 1][2], C[2 * q + 1][3]));
        }

        pr_cur = pr_nxt;
        pr_nxt = pr_n2;
        buf ^= 1;
        grp = next;
    }
}

// ----------------------------------------------------------------------------
extern "C" void kernel_launch(void* const* d_in, const int* in_sizes, int n_in,
                              void* d_out, int out_size) {
    const float* sp     = (const float*)d_in[0];   // [N, 64]
    const float* weight = (const float*)d_in[1];   // [64, 3,3,3, 64]
    const float* bias   = (const float*)d_in[2];   // [64]
    const int2*  nei    = (const int2*)d_in[3];    // [26, P, 2] -> int2 pairs
    const int*   sizes  = (const int*)d_in[4];     // [26]
    float* out = (float*)d_out;

    const int n_vox = in_sizes[0] / CIN;
    const int P     = in_sizes[3] / (NOFFS * 2);

    cudaFuncSetAttribute(scatter_kernel,
                         cudaFuncAttributeMaxDynamicSharedMemorySize,
                         SMEM_SC_BYTES);

    // 1) center tap + bias with plain stores (initializes out)
    {
        int ngroups = (n_vox + CGP - 1) / CGP;
        int blocks  = (ngroups + CWPB - 1) / CWPB;
        if (blocks > 592) blocks = 592;
        center_kernel<<<blocks, CTHREADS, SMEM_C_BYTES>>>(sp, weight, bias,
                                                          out, n_vox);
    }

    // 2) neighbor scatter (stream-ordered after center stores)
    {
        dim3 grid(SGRIDX, NOFFS, 1);
        scatter_kernel<<<grid, STHREADS, SMEM_SC_BYTES>>>(sp, weight, nei,
                                                          sizes, out, P);
    }
}

// round 15
// speedup vs baseline: 1.2483x; 1.1870x over previous
#include <cuda_runtime.h>
#include <cstdint>

#define CIN 64
#define COUT 64
#define NOFFS 26
#define NTAPS 27

// center kernel config
#define CTHREADS 128
#define CWPB (CTHREADS / 32)
#define CGP 32

// scatter kernel config
#define STHREADS 128
#define SWPB (STHREADS / 32)
#define SGP 16
#define SGRIDX 22                  // 22*26 = 572 blocks ≈ 1 wave @ 4/SM

#define BWS_U32 (32 * 32 * 4)                    // 16384 B
#define SBUF_ROW_U32 64                          // 256B rows, XOR-swizzled
#define SBUF_WORDS (2 * SGP * SBUF_ROW_U32)      // per-warp double buffer (2048 u32)
#define SMEM_SC_BYTES ((BWS_U32 + SWPB * SBUF_WORDS) * 4)   // 49152 B
#define SMEM_C_BYTES (BWS_U32 * 4)

typedef uint32_t u32;

// ---- bf16 split helpers -----------------------------------------------------
__device__ __forceinline__ u32 pack_bf16x2(float even, float odd) {
    u32 r;
    asm("cvt.rn.bf16x2.f32 %0, %1, %2;" : "=r"(r) : "f"(odd), "f"(even));
    return r;
}
__device__ __forceinline__ float lo_elem_f(u32 h) { return __uint_as_float(h << 16); }
__device__ __forceinline__ float hi_elem_f(u32 h) { return __uint_as_float(h & 0xffff0000u); }
__device__ __forceinline__ void split2(float e, float o, u32& hp, u32& lp) {
    hp = pack_bf16x2(e, o);
    lp = pack_bf16x2(e - lo_elem_f(hp), o - hi_elem_f(hp));
}

// D += A(16x16 bf16,row) * B(16x8 bf16,col), f32 accumulate
__device__ __forceinline__ void mma_bf16_v(float c[4], u32 a0, u32 a1, u32 a2,
                                           u32 a3, u32 b0, u32 b1) {
    asm volatile(
        "mma.sync.aligned.m16n8k16.row.col.f32.bf16.bf16.f32 "
        "{%0,%1,%2,%3}, {%4,%5,%6,%7}, {%8,%9}, {%0,%1,%2,%3};"
        : "+f"(c[0]), "+f"(c[1]), "+f"(c[2]), "+f"(c[3])
        : "r"(a0), "r"(a1), "r"(a2), "r"(a3), "r"(b0), "r"(b1));
}

// ---- cp.async helpers --------------------------------------------------------
__device__ __forceinline__ u32 smem_u32ptr(const void* p) {
    return (u32)__cvta_generic_to_shared(p);
}
__device__ __forceinline__ void cp_async16(u32 dst, const void* src) {
    asm volatile("cp.async.cg.shared.global [%0], [%1], 16;"
                 :: "r"(dst), "l"(src));
}
__device__ __forceinline__ void cp_commit() {
    asm volatile("cp.async.commit_group;");
}
__device__ __forceinline__ void cp_wait1() {
    asm volatile("cp.async.wait_group 1;");
}

// K-permuted B fragments for tap t.
// Global ci for hw k-position within tile kt: lane tig's four hw k's
// {2tig, 2tig+1, 2tig+8, 2tig+9} map to contiguous global ci = 16kt+4tig+{0..3}.
// Output columns unchanged: n = nt*8 + (lane>>2).
template <int NT>
__device__ __forceinline__ void build_b_tiles(uint4* bws,
                                              const float* __restrict__ weight,
                                              int t) {
    for (int idx = threadIdx.x; idx < 32 * 32; idx += NT) {
        int lane = idx & 31, tile = idx >> 5;
        int kt = tile >> 3, nt = tile & 7;
        int n  = nt * 8 + (lane >> 2);
        int k0 = kt * 16 + 4 * (lane & 3);
        const float* wrow = weight + ((long)n * NTAPS + t) * CIN;
        float4 w = __ldg((const float4*)(wrow + k0));
        u32 bh0, bl0, bh1, bl1;
        split2(w.x, w.y, bh0, bl0);   // hw k = 2tig, 2tig+1
        split2(w.z, w.w, bh1, bl1);   // hw k = 2tig+8, 2tig+9
        bws[idx] = make_uint4(bh0, bh1, bl0, bl1);
    }
}

// ----------------------------------------------------------------------------
// Center kernel: out[v] = bias + sp[v] @ Wc  -- plain stores, initializes out.
// A loads are single LDG.128 per row per kt thanks to the K permutation.
// ----------------------------------------------------------------------------
__global__ __launch_bounds__(CTHREADS, 4)
void center_kernel(const float* __restrict__ sp,
                   const float* __restrict__ weight,
                   const float* __restrict__ bias,
                   float* __restrict__ out, int n_vox) {
    extern __shared__ u32 smem_raw[];
    uint4* bws = (uint4*)smem_raw;

    build_b_tiles<CTHREADS>(bws, weight, 13);
    __syncthreads();

    const int lane = threadIdx.x & 31;
    const int wid  = threadIdx.x >> 5;
    const int tig  = lane & 3;
    const int g    = lane >> 2;

    const int ngroups = (n_vox + CGP - 1) / CGP;

    for (int grp = blockIdx.x * CWPB + wid; grp < ngroups;
         grp += gridDim.x * CWPB) {
        const int base_v = grp * CGP;

        int v0 = base_v + g;        if (v0 >= n_vox) v0 = n_vox - 1;
        int v1 = base_v + g + 8;    if (v1 >= n_vox) v1 = n_vox - 1;
        int v2 = base_v + g + 16;   if (v2 >= n_vox) v2 = n_vox - 1;
        int v3 = base_v + g + 24;   if (v3 >= n_vox) v3 = n_vox - 1;
        const float* r0 = sp + (long)v0 * CIN;
        const float* r1 = sp + (long)v1 * CIN;
        const float* r2 = sp + (long)v2 * CIN;
        const float* r3 = sp + (long)v3 * CIN;

        float C[2][8][4];
#pragma unroll
        for (int m = 0; m < 2; m++)
#pragma unroll
            for (int nt = 0; nt < 8; nt++) {
                C[m][nt][0] = 0.f; C[m][nt][1] = 0.f;
                C[m][nt][2] = 0.f; C[m][nt][3] = 0.f;
            }

#pragma unroll
        for (int kt = 0; kt < 4; kt++) {
            const int c0 = 16 * kt + 4 * tig;
            float4 f0 = __ldg((const float4*)(r0 + c0));
            float4 f1 = __ldg((const float4*)(r1 + c0));
            float4 e0 = __ldg((const float4*)(r2 + c0));
            float4 e1 = __ldg((const float4*)(r3 + c0));

            u32 x0h, x0l, x1h, x1l, x2h, x2l, x3h, x3l;
            split2(f0.x, f0.y, x0h, x0l);
            split2(f1.x, f1.y, x1h, x1l);
            split2(f0.z, f0.w, x2h, x2l);
            split2(f1.z, f1.w, x3h, x3l);
            u32 y0h, y0l, y1h, y1l, y2h, y2l, y3h, y3l;
            split2(e0.x, e0.y, y0h, y0l);
            split2(e1.x, e1.y, y1h, y1l);
            split2(e0.z, e0.w, y2h, y2l);
            split2(e1.z, e1.w, y3h, y3l);

#pragma unroll
            for (int nt = 0; nt < 8; nt++) {
                uint4 b = bws[(kt * 8 + nt) * 32 + lane];
                mma_bf16_v(C[0][nt], x0h, x1h, x2h, x3h, b.x, b.y);
                mma_bf16_v(C[0][nt], x0l, x1l, x2l, x3l, b.x, b.y);
                mma_bf16_v(C[0][nt], x0h, x1h, x2h, x3h, b.z, b.w);
                mma_bf16_v(C[1][nt], y0h, y1h, y2h, y3h, b.x, b.y);
                mma_bf16_v(C[1][nt], y0l, y1l, y2l, y3l, b.x, b.y);
                mma_bf16_v(C[1][nt], y0h, y1h, y2h, y3h, b.z, b.w);
            }
        }

#pragma unroll
        for (int m = 0; m < 2; m++) {
            int w0 = base_v + 16 * m + g;
            int w1 = w0 + 8;
#pragma unroll
            for (int nt = 0; nt < 8; nt++) {
                float2 b = __ldg((const float2*)bias + nt * 4 + tig);
                if (w0 < n_vox)
                    *(float2*)(out + (long)w0 * COUT + nt * 8 + 2 * tig) =
                        make_float2(C[m][nt][0] + b.x, C[m][nt][1] + b.y);
                if (w1 < n_vox)
                    *(float2*)(out + (long)w1 * COUT + nt * 8 + 2 * tig) =
                        make_float2(C[m][nt][2] + b.x, C[m][nt][3] + b.y);
            }
        }
    }
}

// ----------------------------------------------------------------------------
// Scatter kernel: cp.async double-buffered gather; LDS.128 A-reads via the
// K permutation + 64B XOR swizzle (conflict-free); float2 atomic epilogue.
// ----------------------------------------------------------------------------
__global__ __launch_bounds__(STHREADS, 4)
void scatter_kernel(const float* __restrict__ sp,
                    const float* __restrict__ weight,
                    const int2* __restrict__ nei,
                    const int* __restrict__ sizes,
                    float* __restrict__ out, int P) {
    extern __shared__ u32 smem_raw[];
    uint4* bws = (uint4*)smem_raw;

    const int o = blockIdx.y;
    const int t = (o < 13) ? o : o + 1;

    build_b_tiles<STHREADS>(bws, weight, t);
    __syncthreads();

    const int size = sizes[o];
    if (size <= 0) return;
    const long pair_base = (long)o * P;

    const int lane = threadIdx.x & 31;
    const int wid  = threadIdx.x >> 5;
    const int tig  = lane & 3;
    const int g    = lane >> 2;

    // per-warp double buffer: [buf][row][64 u32], rows XOR-swizzled by 64B
    u32* mybuf = smem_raw + BWS_U32 + wid * SBUF_WORDS;
    const int srow_half = lane >> 4;       // 0/1
    const int schunk    = lane & 15;       // 16B chunk within 256B row
    const u32 smem_base = smem_u32ptr(mybuf);

    const int ngroups = (size + SGP - 1) / SGP;
    const int stride  = gridDim.x * SWPB;
    int grp = blockIdx.x * SWPB + wid;
    if (grp >= ngroups) return;

    auto fetch_idx = [&](int gq) -> int2 {
        int p = gq * SGP + lane;
        if (p >= size) p = size - 1;
        int2 r = make_int2(0, 0);
        if (lane < SGP) r = __ldg(&nei[pair_base + p]);
        return r;
    };

    auto issue_group = [&](int2 pr, int b) {
        u32 base = smem_base + (u32)b * (SGP * SBUF_ROW_U32 * 4);
#pragma unroll
        for (int i = 0; i < 8; i++) {
            int row = 2 * i + srow_half;
            int ii  = __shfl_sync(0xffffffffu, pr.y, row);
            u32 off = row * 256 + ((schunk * 16) ^ ((row & 1) * 64));
            cp_async16(base + off, sp + (long)ii * CIN + schunk * 4);
        }
    };

    int2 pr_cur = fetch_idx(grp);
    issue_group(pr_cur, 0);
    cp_commit();
    int2 pr_nxt = make_int2(0, 0);
    if (grp + stride < ngroups) pr_nxt = fetch_idx(grp + stride);

    int buf = 0;
    for (; grp < ngroups;) {
        const int next = grp + stride;

        if (next < ngroups) issue_group(pr_nxt, buf ^ 1);
        cp_commit();

        int2 pr_n2 = make_int2(0, 0);
        if (next + stride < ngroups) pr_n2 = fetch_idx(next + stride);

        cp_wait1();
        __syncwarp();

        const int base_p = grp * SGP;
        const float* rows = (const float*)(mybuf + buf * (SGP * SBUF_ROW_U32));
        const u32 kxor = (g & 1) * 16;     // row parity same for g and g+8

        float C[8][4];
#pragma unroll
        for (int nt = 0; nt < 8; nt++) {
            C[nt][0] = 0.f; C[nt][1] = 0.f; C[nt][2] = 0.f; C[nt][3] = 0.f;
        }

#pragma unroll
        for (int kt = 0; kt < 4; kt++) {
            const u32 kidx = (u32)(16 * kt + 4 * tig) ^ kxor;
            float4 f0 = *(const float4*)(rows + g * 64 + kidx);
            float4 f1 = *(const float4*)(rows + (g + 8) * 64 + kidx);

            u32 x0h, x0l, x1h, x1l, x2h, x2l, x3h, x3l;
            split2(f0.x, f0.y, x0h, x0l);
            split2(f1.x, f1.y, x1h, x1l);
            split2(f0.z, f0.w, x2h, x2l);
            split2(f1.z, f1.w, x3h, x3l);

#pragma unroll
            for (int nt = 0; nt < 8; nt++) {
                uint4 b = bws[(kt * 8 + nt) * 32 + lane];
                mma_bf16_v(C[nt], x0h, x1h, x2h, x3h, b.x, b.y);  // Ah*Bh
                mma_bf16_v(C[nt], x0l, x1l, x2l, x3l, b.x, b.y);  // Al*Bh
                mma_bf16_v(C[nt], x0h, x1h, x2h, x3h, b.z, b.w);  // Ah*Bl
            }
        }

        // atomic scatter: rows g (c0,c1) and g+8 (c2,c3)
        int oi0 = __shfl_sync(0xffffffffu, pr_cur.x, g);
        int oi1 = __shfl_sync(0xffffffffu, pr_cur.x, g + 8);
        bool v0 = (base_p + g)     < size;
        bool v1 = (base_p + g + 8) < size;
        float* o0 = out + (long)oi0 * COUT + 2 * tig;
        float* o1 = out + (long)oi1 * COUT + 2 * tig;
#pragma unroll
        for (int nt = 0; nt < 8; nt++) {
            if (v0)
                atomicAdd((float2*)(o0 + nt * 8),
                          make_float2(C[nt][0], C[nt][1]));
            if (v1)
                atomicAdd((float2*)(o1 + nt * 8),
                          make_float2(C[nt][2], C[nt][3]));
        }

        pr_cur = pr_nxt;
        pr_nxt = pr_n2;
        buf ^= 1;
        grp = next;
    }
}

// ----------------------------------------------------------------------------
extern "C" void kernel_launch(void* const* d_in, const int* in_sizes, int n_in,
                              void* d_out, int out_size) {
    const float* sp     = (const float*)d_in[0];   // [N, 64]
    const float* weight = (const float*)d_in[1];   // [64, 3,3,3, 64]
    const float* bias   = (const float*)d_in[2];   // [64]
    const int2*  nei    = (const int2*)d_in[3];    // [26, P, 2] -> int2 pairs
    const int*   sizes  = (const int*)d_in[4];     // [26]
    float* out = (float*)d_out;

    const int n_vox = in_sizes[0] / CIN;
    const int P     = in_sizes[3] / (NOFFS * 2);

    cudaFuncSetAttribute(scatter_kernel,
                         cudaFuncAttributeMaxDynamicSharedMemorySize,
                         SMEM_SC_BYTES);

    // 1) center tap + bias with plain stores (initializes out)
    {
        int ngroups = (n_vox + CGP - 1) / CGP;
        int blocks  = (ngroups + CWPB - 1) / CWPB;
        if (blocks > 592) blocks = 592;
        center_kernel<<<blocks, CTHREADS, SMEM_C_BYTES>>>(sp, weight, bias,
                                                          out, n_vox);
    }

    // 2) neighbor scatter (stream-ordered after center stores)
    {
        dim3 grid(SGRIDX, NOFFS, 1);
        scatter_kernel<<<grid, STHREADS, SMEM_SC_BYTES>>>(sp, weight, nei,
                                                          sizes, out, P);
    }
}

// round 16
// speedup vs baseline: 1.3028x; 1.0437x over previous
#include <cuda_runtime.h>
#include <cstdint>

#define CIN 64
#define COUT 64
#define NOFFS 26
#define NTAPS 27

// center kernel config
#define CTHREADS 128
#define CWPB (CTHREADS / 32)
#define CGP 32

// scatter kernel config
#define STHREADS 128
#define SWPB (STHREADS / 32)
#define SGP 16
#define SGRIDX 22                  // 22*26 = 572 blocks ≈ 1 wave @ 4/SM

#define BWS_U32 (32 * 32 * 4)                    // 16384 B
#define SBUF_ROW_U32 64                          // 256B rows, XOR-swizzled
#define SBUF_WORDS (2 * SGP * SBUF_ROW_U32)      // per-warp double buffer (2048 u32)
#define SMEM_SC_BYTES ((BWS_U32 + SWPB * SBUF_WORDS) * 4)   // 49152 B
#define SMEM_C_BYTES (BWS_U32 * 4)

typedef uint32_t u32;

// ---- bf16 split helpers -----------------------------------------------------
__device__ __forceinline__ u32 pack_bf16x2(float even, float odd) {
    u32 r;
    asm("cvt.rn.bf16x2.f32 %0, %1, %2;" : "=r"(r) : "f"(odd), "f"(even));
    return r;
}
__device__ __forceinline__ float lo_elem_f(u32 h) { return __uint_as_float(h << 16); }
__device__ __forceinline__ float hi_elem_f(u32 h) { return __uint_as_float(h & 0xffff0000u); }
__device__ __forceinline__ void split2(float e, float o, u32& hp, u32& lp) {
    hp = pack_bf16x2(e, o);
    lp = pack_bf16x2(e - lo_elem_f(hp), o - hi_elem_f(hp));
}

// D += A(16x16 bf16,row) * B(16x8 bf16,col), f32 accumulate
__device__ __forceinline__ void mma_bf16_v(float c[4], u32 a0, u32 a1, u32 a2,
                                           u32 a3, u32 b0, u32 b1) {
    asm volatile(
        "mma.sync.aligned.m16n8k16.row.col.f32.bf16.bf16.f32 "
        "{%0,%1,%2,%3}, {%4,%5,%6,%7}, {%8,%9}, {%0,%1,%2,%3};"
        : "+f"(c[0]), "+f"(c[1]), "+f"(c[2]), "+f"(c[3])
        : "r"(a0), "r"(a1), "r"(a2), "r"(a3), "r"(b0), "r"(b1));
}

// ---- cp.async helpers --------------------------------------------------------
__device__ __forceinline__ u32 smem_u32ptr(const void* p) {
    return (u32)__cvta_generic_to_shared(p);
}
__device__ __forceinline__ void cp_async16(u32 dst, const void* src) {
    asm volatile("cp.async.cg.shared.global [%0], [%1], 16;"
                 :: "r"(dst), "l"(src));
}
__device__ __forceinline__ void cp_commit() {
    asm volatile("cp.async.commit_group;");
}
__device__ __forceinline__ void cp_wait1() {
    asm volatile("cp.async.wait_group 1;");
}

// K-permuted B fragments for tap t.
// Lane tig's four hw k's {2tig, 2tig+1, 2tig+8, 2tig+9} map to contiguous
// global ci = 16kt + 4tig + {0..3}. Output cols: n = nt*8 + (lane>>2).
template <int NT>
__device__ __forceinline__ void build_b_tiles(uint4* bws,
                                              const float* __restrict__ weight,
                                              int t) {
    for (int idx = threadIdx.x; idx < 32 * 32; idx += NT) {
        int lane = idx & 31, tile = idx >> 5;
        int kt = tile >> 3, nt = tile & 7;
        int n  = nt * 8 + (lane >> 2);
        int k0 = kt * 16 + 4 * (lane & 3);
        const float* wrow = weight + ((long)n * NTAPS + t) * CIN;
        float4 w = __ldg((const float4*)(wrow + k0));
        u32 bh0, bl0, bh1, bl1;
        split2(w.x, w.y, bh0, bl0);
        split2(w.z, w.w, bh1, bl1);
        bws[idx] = make_uint4(bh0, bh1, bl0, bl1);
    }
}

// ----------------------------------------------------------------------------
// Center kernel: out[v] = bias + sp[v] @ Wc  -- plain stores, initializes out.
// Triggers programmatic launch completion so scatter's prologue overlaps.
// ----------------------------------------------------------------------------
__global__ __launch_bounds__(CTHREADS, 4)
void center_kernel(const float* __restrict__ sp,
                   const float* __restrict__ weight,
                   const float* __restrict__ bias,
                   float* __restrict__ out, int n_vox) {
    extern __shared__ u32 smem_raw[];
    uint4* bws = (uint4*)smem_raw;

    build_b_tiles<CTHREADS>(bws, weight, 13);
    __syncthreads();

    const int lane = threadIdx.x & 31;
    const int wid  = threadIdx.x >> 5;
    const int tig  = lane & 3;
    const int g    = lane >> 2;

    const int ngroups = (n_vox + CGP - 1) / CGP;

    for (int grp = blockIdx.x * CWPB + wid; grp < ngroups;
         grp += gridDim.x * CWPB) {
        const int base_v = grp * CGP;

        int v0 = base_v + g;        if (v0 >= n_vox) v0 = n_vox - 1;
        int v1 = base_v + g + 8;    if (v1 >= n_vox) v1 = n_vox - 1;
        int v2 = base_v + g + 16;   if (v2 >= n_vox) v2 = n_vox - 1;
        int v3 = base_v + g + 24;   if (v3 >= n_vox) v3 = n_vox - 1;
        const float* r0 = sp + (long)v0 * CIN;
        const float* r1 = sp + (long)v1 * CIN;
        const float* r2 = sp + (long)v2 * CIN;
        const float* r3 = sp + (long)v3 * CIN;

        float C[2][8][4];
#pragma unroll
        for (int m = 0; m < 2; m++)
#pragma unroll
            for (int nt = 0; nt < 8; nt++) {
                C[m][nt][0] = 0.f; C[m][nt][1] = 0.f;
                C[m][nt][2] = 0.f; C[m][nt][3] = 0.f;
            }

#pragma unroll
        for (int kt = 0; kt < 4; kt++) {
            const int c0 = 16 * kt + 4 * tig;
            float4 f0 = __ldg((const float4*)(r0 + c0));
            float4 f1 = __ldg((const float4*)(r1 + c0));
            float4 e0 = __ldg((const float4*)(r2 + c0));
            float4 e1 = __ldg((const float4*)(r3 + c0));

            u32 x0h, x0l, x1h, x1l, x2h, x2l, x3h, x3l;
            split2(f0.x, f0.y, x0h, x0l);
            split2(f1.x, f1.y, x1h, x1l);
            split2(f0.z, f0.w, x2h, x2l);
            split2(f1.z, f1.w, x3h, x3l);
            u32 y0h, y0l, y1h, y1l, y2h, y2l, y3h, y3l;
            split2(e0.x, e0.y, y0h, y0l);
            split2(e1.x, e1.y, y1h, y1l);
            split2(e0.z, e0.w, y2h, y2l);
            split2(e1.z, e1.w, y3h, y3l);

#pragma unroll
            for (int nt = 0; nt < 8; nt++) {
                uint4 b = bws[(kt * 8 + nt) * 32 + lane];
                mma_bf16_v(C[0][nt], x0h, x1h, x2h, x3h, b.x, b.y);
                mma_bf16_v(C[0][nt], x0l, x1l, x2l, x3l, b.x, b.y);
                mma_bf16_v(C[0][nt], x0h, x1h, x2h, x3h, b.z, b.w);
                mma_bf16_v(C[1][nt], y0h, y1h, y2h, y3h, b.x, b.y);
                mma_bf16_v(C[1][nt], y0l, y1l, y2l, y3l, b.x, b.y);
                mma_bf16_v(C[1][nt], y0h, y1h, y2h, y3h, b.z, b.w);
            }
        }

#pragma unroll
        for (int m = 0; m < 2; m++) {
            int w0 = base_v + 16 * m + g;
            int w1 = w0 + 8;
#pragma unroll
            for (int nt = 0; nt < 8; nt++) {
                float2 b = __ldg((const float2*)bias + nt * 4 + tig);
                if (w0 < n_vox)
                    *(float2*)(out + (long)w0 * COUT + nt * 8 + 2 * tig) =
                        make_float2(C[m][nt][0] + b.x, C[m][nt][1] + b.y);
                if (w1 < n_vox)
                    *(float2*)(out + (long)w1 * COUT + nt * 8 + 2 * tig) =
                        make_float2(C[m][nt][2] + b.x, C[m][nt][3] + b.y);
            }
        }
    }

    // All of this block's stores are issued; allow the scatter kernel's
    // prologue to begin (PDL trigger has implicit memory-visibility semantics
    // paired with cudaGridDependencySynchronize in the secondary).
    cudaTriggerProgrammaticLaunchCompletion();
}

// ----------------------------------------------------------------------------
// Scatter kernel: cp.async double-buffered gather; LDS.128 A-reads via the
// K permutation + 64B XOR swizzle; float2 atomic epilogue.
// PDL: everything before the first atomicAdd is independent of `out`, so the
// grid-dependency sync sits right before the main loop.
// ----------------------------------------------------------------------------
__global__ __launch_bounds__(STHREADS, 4)
void scatter_kernel(const float* __restrict__ sp,
                    const float* __restrict__ weight,
                    const int2* __restrict__ nei,
                    const int* __restrict__ sizes,
                    float* __restrict__ out, int P) {
    extern __shared__ u32 smem_raw[];
    uint4* bws = (uint4*)smem_raw;

    const int o = blockIdx.y;
    const int t = (o < 13) ? o : o + 1;

    build_b_tiles<STHREADS>(bws, weight, t);
    __syncthreads();

    const int size = sizes[o];
    if (size <= 0) return;
    const long pair_base = (long)o * P;

    const int lane = threadIdx.x & 31;
    const int wid  = threadIdx.x >> 5;
    const int tig  = lane & 3;
    const int g    = lane >> 2;

    u32* mybuf = smem_raw + BWS_U32 + wid * SBUF_WORDS;
    const int srow_half = lane >> 4;
    const int schunk    = lane & 15;
    const u32 smem_base = smem_u32ptr(mybuf);

    const int ngroups = (size + SGP - 1) / SGP;
    const int stride  = gridDim.x * SWPB;
    int grp = blockIdx.x * SWPB + wid;
    if (grp >= ngroups) {
        cudaGridDependencySynchronize();   // still honor the dependency
        return;
    }

    auto fetch_idx = [&](int gq) -> int2 {
        int p = gq * SGP + lane;
        if (p >= size) p = size - 1;
        int2 r = make_int2(0, 0);
        if (lane < SGP) r = __ldg(&nei[pair_base + p]);
        return r;
    };

    auto issue_group = [&](int2 pr, int b) {
        u32 base = smem_base + (u32)b * (SGP * SBUF_ROW_U32 * 4);
#pragma unroll
        for (int i = 0; i < 8; i++) {
            int row = 2 * i + srow_half;
            int ii  = __shfl_sync(0xffffffffu, pr.y, row);
            u32 off = row * 256 + ((schunk * 16) ^ ((row & 1) * 64));
            cp_async16(base + off, sp + (long)ii * CIN + schunk * 4);
        }
    };

    int2 pr_cur = fetch_idx(grp);
    issue_group(pr_cur, 0);
    cp_commit();
    int2 pr_nxt = make_int2(0, 0);
    if (grp + stride < ngroups) pr_nxt = fetch_idx(grp + stride);

    // Wait for the center kernel's stores to out before the first atomicAdd.
    cudaGridDependencySynchronize();

    int buf = 0;
    for (; grp < ngroups;) {
        const int next = grp + stride;

        if (next < ngroups) issue_group(pr_nxt, buf ^ 1);
        cp_commit();

        int2 pr_n2 = make_int2(0, 0);
        if (next + stride < ngroups) pr_n2 = fetch_idx(next + stride);

        cp_wait1();
        __syncwarp();

        const int base_p = grp * SGP;
        const float* rows = (const float*)(mybuf + buf * (SGP * SBUF_ROW_U32));
        const u32 kxor = (g & 1) * 16;

        float C[8][4];
#pragma unroll
        for (int nt = 0; nt < 8; nt++) {
            C[nt][0] = 0.f; C[nt][1] = 0.f; C[nt][2] = 0.f; C[nt][3] = 0.f;
        }

#pragma unroll
        for (int kt = 0; kt < 4; kt++) {
            const u32 kidx = (u32)(16 * kt + 4 * tig) ^ kxor;
            float4 f0 = *(const float4*)(rows + g * 64 + kidx);
            float4 f1 = *(const float4*)(rows + (g + 8) * 64 + kidx);

            u32 x0h, x0l, x1h, x1l, x2h, x2l, x3h, x3l;
            split2(f0.x, f0.y, x0h, x0l);
            split2(f1.x, f1.y, x1h, x1l);
            split2(f0.z, f0.w, x2h, x2l);
            split2(f1.z, f1.w, x3h, x3l);

#pragma unroll
            for (int nt = 0; nt < 8; nt++) {
                uint4 b = bws[(kt * 8 + nt) * 32 + lane];
                mma_bf16_v(C[nt], x0h, x1h, x2h, x3h, b.x, b.y);  // Ah*Bh
                mma_bf16_v(C[nt], x0l, x1l, x2l, x3l, b.x, b.y);  // Al*Bh
                mma_bf16_v(C[nt], x0h, x1h, x2h, x3h, b.z, b.w);  // Ah*Bl
            }
        }

        int oi0 = __shfl_sync(0xffffffffu, pr_cur.x, g);
        int oi1 = __shfl_sync(0xffffffffu, pr_cur.x, g + 8);
        bool v0 = (base_p + g)     < size;
        bool v1 = (base_p + g + 8) < size;
        float* o0 = out + (long)oi0 * COUT + 2 * tig;
        float* o1 = out + (long)oi1 * COUT + 2 * tig;
#pragma unroll
        for (int nt = 0; nt < 8; nt++) {
            if (v0)
                atomicAdd((float2*)(o0 + nt * 8),
                          make_float2(C[nt][0], C[nt][1]));
            if (v1)
                atomicAdd((float2*)(o1 + nt * 8),
                          make_float2(C[nt][2], C[nt][3]));
        }

        pr_cur = pr_nxt;
        pr_nxt = pr_n2;
        buf ^= 1;
        grp = next;
    }
}

// ----------------------------------------------------------------------------
extern "C" void kernel_launch(void* const* d_in, const int* in_sizes, int n_in,
                              void* d_out, int out_size) {
    const float* sp     = (const float*)d_in[0];   // [N, 64]
    const float* weight = (const float*)d_in[1];   // [64, 3,3,3, 64]
    const float* bias   = (const float*)d_in[2];   // [64]
    const int2*  nei    = (const int2*)d_in[3];    // [26, P, 2] -> int2 pairs
    const int*   sizes  = (const int*)d_in[4];     // [26]
    float* out = (float*)d_out;

    const int n_vox = in_sizes[0] / CIN;
    const int P     = in_sizes[3] / (NOFFS * 2);

    cudaFuncSetAttribute(scatter_kernel,
                         cudaFuncAttributeMaxDynamicSharedMemorySize,
                         SMEM_SC_BYTES);

    // 1) center tap + bias with plain stores (initializes out)
    {
        int ngroups = (n_vox + CGP - 1) / CGP;
        int blocks  = (ngroups + CWPB - 1) / CWPB;
        if (blocks > 592) blocks = 592;
        center_kernel<<<blocks, CTHREADS, SMEM_C_BYTES>>>(sp, weight, bias,
                                                          out, n_vox);
    }

    // 2) neighbor scatter with programmatic dependent launch: its prologue
    //    (B build + first gathers) overlaps the center kernel's tail.
    {
        cudaLaunchConfig_t cfg = {};
        cfg.gridDim = dim3(SGRIDX, NOFFS, 1);
        cfg.blockDim = dim3(STHREADS, 1, 1);
        cfg.dynamicSmemBytes = SMEM_SC_BYTES;
        cfg.stream = 0;
        cudaLaunchAttribute attr[1];
        attr[0].id = cudaLaunchAttributeProgrammaticStreamSerialization;
        attr[0].val.programmaticStreamSerializationAllowed = 1;
        cfg.attrs = attr;
        cfg.numAttrs = 1;
        cudaLaunchKernelEx(&cfg, scatter_kernel, sp, weight, nei, sizes,
                           out, P);
    }
}